// round 11
// baseline (speedup 1.0000x reference)
#include <cuda_runtime.h>
#include <cstdint>

#define B_ 8
#define H_ 1024
#define W_ 1024
#define HW_ (H_*W_)
#define K_ 2048
#define SURV_ 4096
#define NBIN_ 2048
#define NBUCK_ 128
#define CAPB_ 8192
#define NCELL_ 1024   /* 32x32 grid */
#define CELL_INV (1.0f/256.0f)
#define EMAX_ 512
#define RPB_ 16       /* rows per block in k_cand */
#define SBUF_ 2048    /* per-block candidate staging */

// ---------------- scratch (static device memory only) ----------------
__device__ unsigned long long g_bcand[B_][NBUCK_][CAPB_];  // bucketed candidates
__device__ unsigned g_bcnt[B_][NBUCK_];                    // zeroed by k_post each call
__device__ unsigned long long g_topk[B_][K_];

// ---------------- K1: local-max candidates (paired separable max9, bucketed emit) ----------------
// block = 16 image rows (256 threads x 4 px), grid = (H/16, B)
__global__ void __launch_bounds__(256) k_cand(const float* __restrict__ sc) {
    const int b = blockIdx.y, h0 = blockIdx.x * RPB_;
    const int tid = threadIdx.x;
    const int w0 = tid * 4;
    const int lane = tid & 31;
    const float NI = -__int_as_float(0x7f800000); // -inf

    __shared__ int scnt;
    __shared__ unsigned long long sbuf[SBUF_];
    __shared__ unsigned scntb[NBUCK_];
    __shared__ unsigned sbase[NBUCK_];
    __shared__ unsigned scur[NBUCK_];
    if (tid < NBUCK_) { scntb[tid] = 0u; scur[tid] = 0u; }
    if (tid == 0) scnt = 0;
    __syncthreads();

    float v[6];
    float h3m[4], h3c[4], h3n[4], h3n2[4];
    float cenc[4], cenn[4], cenn2[4];

    #define LOADROW(hh) do {                                                \
        int _h = (hh);                                                      \
        if ((unsigned)_h >= (unsigned)H_) {                                 \
            v[0]=NI; v[1]=NI; v[2]=NI; v[3]=NI; v[4]=NI; v[5]=NI;           \
        } else {                                                            \
            const float* _r = sc + ((size_t)b * H_ + _h) * W_;              \
            float4 _m = *reinterpret_cast<const float4*>(_r + w0);          \
            float _lw = __shfl_up_sync(0xffffffffu, _m.w, 1);               \
            float _rx = __shfl_down_sync(0xffffffffu, _m.x, 1);             \
            v[1]=_m.x; v[2]=_m.y; v[3]=_m.z; v[4]=_m.w;                     \
            v[0] = lane        ? _lw : ((w0 > 0)      ? _r[w0-1] : NI);     \
            v[5] = (lane != 31)? _rx : ((w0 + 4 < W_) ? _r[w0+4] : NI);     \
        }                                                                   \
    } while (0)
    // horizontal 3-max with shared pair-maxes: 7 fmax / 4 px
    #define H3(d) do {                                                      \
        float _q0 = fmaxf(v[0], v[1]);                                      \
        float _q2 = fmaxf(v[2], v[3]);                                      \
        float _q4 = fmaxf(v[4], v[5]);                                      \
        d[0] = fmaxf(_q0, v[2]);                                            \
        d[1] = fmaxf(v[1], _q2);                                            \
        d[2] = fmaxf(_q2, v[4]);                                            \
        d[3] = fmaxf(v[3], _q4);                                            \
    } while (0)
    #define EMIT(s_, hh_, p_) do {                                          \
        int _pos = atomicAdd(&scnt, 1);                                     \
        if (_pos < SBUF_) {                                                 \
            unsigned _idx = (unsigned)((hh_) * W_ + w0 + (p_));             \
            unsigned _sb = __float_as_uint(s_);                             \
            sbuf[_pos] = ((unsigned long long)_sb << 32) | (unsigned)(~_idx);\
        }                                                                   \
    } while (0)

    LOADROW(h0 - 1); H3(h3m);
    LOADROW(h0);     H3(h3c); cenc[0]=v[1]; cenc[1]=v[2]; cenc[2]=v[3]; cenc[3]=v[4];

    #pragma unroll
    for (int r = 0; r < RPB_; r += 2) {
        LOADROW(h0 + r + 1); H3(h3n);  cenn[0]=v[1];  cenn[1]=v[2];  cenn[2]=v[3];  cenn[3]=v[4];
        LOADROW(h0 + r + 2); H3(h3n2); cenn2[0]=v[1]; cenn2[1]=v[2]; cenn2[2]=v[3]; cenn2[3]=v[4];
        #pragma unroll
        for (int p = 0; p < 4; p++) {
            float vp = fmaxf(h3c[p], h3n[p]);           // rows r, r+1 vertical pair
            float pool0 = fmaxf(h3m[p], vp);            // rows r-1..r+1
            float s0v = cenc[p];
            if (s0v > 0.5f && s0v == pool0) EMIT(s0v, h0 + r, p);
            float pool1 = fmaxf(vp, h3n2[p]);           // rows r..r+2
            float s1v = cenn[p];
            if (s1v > 0.5f && s1v == pool1) EMIT(s1v, h0 + r + 1, p);
        }
        #pragma unroll
        for (int q = 0; q < 4; q++) { h3m[q]=h3n[q]; h3c[q]=h3n2[q]; cenc[q]=cenn2[q]; }
    }
    __syncthreads();

    int c = scnt < SBUF_ ? scnt : SBUF_;
    // pass 0: per-bucket counts
    for (int i = tid; i < c; i += 256) {
        int bu = (int)((unsigned)(sbuf[i] >> 48) & (NBUCK_-1));
        atomicAdd(&scntb[bu], 1u);
    }
    __syncthreads();
    // reserve global ranges per non-empty bucket
    if (tid < NBUCK_) {
        unsigned cnt = scntb[tid];
        if (cnt) sbase[tid] = atomicAdd(&g_bcnt[b][tid], cnt);
    }
    __syncthreads();
    // pass 1: scatter to global buckets
    for (int i = tid; i < c; i += 256) {
        unsigned long long key = sbuf[i];
        int bu = (int)((unsigned)(key >> 48) & (NBUCK_-1));
        unsigned pos = atomicAdd(&scur[bu], 1u) + sbase[bu];
        if (pos < CAPB_) g_bcand[b][bu][pos] = key;
    }
    #undef LOADROW
    #undef H3
    #undef EMIT
}

// ---------------- K2: fused select + rank + decode + NMS + outputs ----------------
// one CTA per batch, 1024 threads; all intermediate state in shared
struct PhA {
    unsigned long long surv[SURV_];   // 32 KB
    unsigned sfx[NBIN_];              // 8 KB  (hist -> suffix -> cursors -> ends)
    unsigned bcnt[NBUCK_];            // 0.5 KB
};
struct PhB {
    float bx1[K_], by1[K_], bx2[K_], by2[K_];  // 32 KB
    unsigned cellcnt[NCELL_];                  // 4 KB
    unsigned short cstart[NCELL_ + 2];         // 2 KB
    unsigned short list[K_];                   // 4 KB
    unsigned char keep[K_];                    // 2 KB
    unsigned edges[EMAX_];                     // 2 KB
    unsigned wsum[32];
};

__global__ void __launch_bounds__(1024) k_post(
    const float* __restrict__ deltas, const float* __restrict__ sizes,
    const int* __restrict__ p_stride, const int* __restrict__ p_offy,
    const int* __restrict__ p_offx,
    float* __restrict__ out, int out_size)
{
    const int b = blockIdx.x, tid = threadIdx.x;
    const int wid = tid >> 5, lane = tid & 31;
    __shared__ union { PhA a; PhB bb; } u;
    __shared__ int sB, sT, sM, sE;

    // ---- phase A1: load + zero bucket counters, zero hist, zero topk ----
    if (tid < NBUCK_) {
        unsigned c = g_bcnt[b][tid];
        u.a.bcnt[tid] = c < CAPB_ ? c : CAPB_;
        g_bcnt[b][tid] = 0u;                    // reset for next call
    }
    u.a.sfx[tid] = 0u; u.a.sfx[tid + 1024] = 0u;
    for (int i = tid; i < K_; i += 1024) g_topk[b][i] = 0ull;
    if (tid == 0) sT = 0;
    __syncthreads();

    // ---- A2: coarse threshold bucket ----
    if (tid == 0) {
        unsigned acc = 0; int Bst = 0;
        for (int bu = NBUCK_-1; bu >= 0; bu--) {
            acc += u.a.bcnt[bu];
            if (acc >= K_) { Bst = bu; break; }
        }
        sB = Bst;
    }
    __syncthreads();
    const int Bst = sB;

    // ---- A3: fine histogram over surviving buckets ----
    for (int bu = Bst; bu < NBUCK_; bu++) {
        int cnt = (int)u.a.bcnt[bu];
        for (int i = tid; i < cnt; i += 1024) {
            unsigned long long key = g_bcand[b][bu][i];
            atomicAdd(&u.a.sfx[(unsigned)(key >> 44) & (NBIN_-1)], 1u);
        }
    }
    __syncthreads();

    // ---- A4: inclusive suffix sums: sfx[i] = #keys with bin >= i ----
    for (int off = 1; off < NBIN_; off <<= 1) {
        unsigned v0 = u.a.sfx[tid]      + ((tid + off        < NBIN_) ? u.a.sfx[tid + off]        : 0u);
        unsigned v1 = u.a.sfx[tid+1024] + ((tid + 1024 + off < NBIN_) ? u.a.sfx[tid + 1024 + off] : 0u);
        __syncthreads();
        u.a.sfx[tid] = v0; u.a.sfx[tid + 1024] = v1;
        __syncthreads();
    }

    // ---- A5: threshold bin T ----
    for (int i = tid; i < NBIN_; i += 1024) {
        unsigned s = u.a.sfx[i];
        unsigned nx = (i + 1 < NBIN_) ? u.a.sfx[i+1] : 0u;
        if (s >= K_ && nx < K_) sT = i;
    }
    __syncthreads();
    const int T = sT;

    // ---- A6: convert sfx to scatter cursors (cur[bin] = sfx[bin+1]); save M ----
    unsigned r0 = (tid + 1    < NBIN_) ? u.a.sfx[tid + 1]    : 0u;
    unsigned r1 = (tid + 1025 < NBIN_) ? u.a.sfx[tid + 1025] : 0u;
    if (tid == 0) { unsigned M = u.a.sfx[T]; sM = (int)(M < SURV_ ? M : SURV_); }
    __syncthreads();
    u.a.sfx[tid] = r0; u.a.sfx[tid + 1024] = r1;
    __syncthreads();
    const int M = sM;

    // ---- A7: bin-grouped compaction into shared ----
    for (int bu = Bst; bu < NBUCK_; bu++) {
        int cnt = (int)u.a.bcnt[bu];
        for (int i = tid; i < cnt; i += 1024) {
            unsigned long long key = g_bcand[b][bu][i];
            int bin = (int)((unsigned)(key >> 44) & (NBIN_-1));
            if (bin >= T) {
                unsigned pos = atomicAdd(&u.a.sfx[bin], 1u);
                if (pos < SURV_) u.a.surv[pos] = key;
            }
        }
    }
    __syncthreads();
    // after scatter: sfx[bin] == segment end for bins >= T; start = sfx[bin+1]

    // ---- A8: warp-cooperative exact rank; lane0 scatters key to g_topk ----
    for (int t = wid; t < M; t += 32) {
        unsigned long long key = u.a.surv[t];
        int bin = (int)((unsigned)(key >> 44) & (NBIN_-1));
        unsigned s0 = (bin + 1 < NBIN_) ? u.a.sfx[bin + 1] : 0u;
        unsigned e  = u.a.sfx[bin]; if (e > SURV_) e = SURV_;
        unsigned cnt = 0;
        for (unsigned mb = s0; mb < e; mb += 32) {
            unsigned m = mb + lane;
            bool g = (m < e) && (u.a.surv[m] > key);
            cnt += __popc(__ballot_sync(0xffffffffu, g));
        }
        unsigned rank = s0 + cnt;
        if (lane == 0 && rank < K_) g_topk[b][rank] = key;
    }
    __syncthreads();

    // ---- phase B: decode + cell binning (phase A shared now dead) ----
    u.bb.cellcnt[tid] = 0u;
    if (tid == 0) sE = 0;
    __syncthreads();

    const int stride = *p_stride, offy = *p_offy, offx = *p_offx;
    for (int t = tid; t < K_; t += 1024) {
        unsigned long long key = g_topk[b][t];
        bool valid = key != 0ull;
        float x1=0.f, y1=0.f, x2=0.f, y2=0.f;
        if (valid) {
            unsigned idx = ~(unsigned)key;
            int iw = (int)(idx & (W_-1)), ih = (int)(idx >> 10);
            float dx = deltas[((size_t)b*2 + 0)*HW_ + idx];
            float dy = deltas[((size_t)b*2 + 1)*HW_ + idx];
            float sx = sizes [((size_t)b*2 + 0)*HW_ + idx];
            float sy = sizes [((size_t)b*2 + 1)*HW_ + idx];
            float cx = (float)(iw*stride + offx) + dx;
            float cy = (float)(ih*stride + offy) + dy;
            x1 = cx - sx*0.5f; x2 = cx + sx*0.5f;
            y1 = cy - sy*0.5f; y2 = cy + sy*0.5f;
        }
        u.bb.bx1[t]=x1; u.bb.by1[t]=y1; u.bb.bx2[t]=x2; u.bb.by2[t]=y2;
        u.bb.keep[t] = valid ? 1 : 0;
        if (valid) {
            int ccx = min(31, max(0, (int)floorf((x1+x2)*0.5f*CELL_INV)));
            int ccy = min(31, max(0, (int)floorf((y1+y2)*0.5f*CELL_INV)));
            atomicAdd(&u.bb.cellcnt[ccy*32 + ccx], 1u);
        }
    }
    __syncthreads();

    // ---- B2: exclusive scan over 1024 cells ----
    {
        unsigned orig = u.bb.cellcnt[tid];
        unsigned x = orig;
        for (int o = 1; o < 32; o <<= 1) {
            unsigned y = __shfl_up_sync(0xffffffffu, x, o);
            if (lane >= o) x += y;
        }
        if (lane == 31) u.bb.wsum[wid] = x;
        __syncthreads();
        if (wid == 0) {
            unsigned s2 = u.bb.wsum[lane];
            for (int o = 1; o < 32; o <<= 1) {
                unsigned y = __shfl_up_sync(0xffffffffu, s2, o);
                if (lane >= o) s2 += y;
            }
            u.bb.wsum[lane] = s2;
        }
        __syncthreads();
        unsigned incl = x + (wid > 0 ? u.bb.wsum[wid-1] : 0u);
        unsigned excl = incl - orig;
        u.bb.cstart[tid] = (unsigned short)excl;
        if (tid == NCELL_-1) u.bb.cstart[NCELL_] = (unsigned short)incl;
        __syncthreads();
        u.bb.cellcnt[tid] = excl;   // becomes scatter cursor
    }
    __syncthreads();

    // ---- B3: scatter into cell-sorted list ----
    for (int t = tid; t < K_; t += 1024) {
        if (u.bb.keep[t]) {
            int ccx = min(31, max(0, (int)floorf((u.bb.bx1[t]+u.bb.bx2[t])*0.5f*CELL_INV)));
            int ccy = min(31, max(0, (int)floorf((u.bb.by1[t]+u.bb.by2[t])*0.5f*CELL_INV)));
            unsigned p = atomicAdd(&u.bb.cellcnt[ccy*32 + ccx], 1u);
            u.bb.list[p] = (unsigned short)t;
        }
    }
    __syncthreads();

    // ---- B4: sparse edge detection: (i<j) with IoU > 0.5 via 3x3 cell hood ----
    for (int t = tid; t < K_; t += 1024) {
        if (!u.bb.keep[t]) continue;
        float jx1=u.bb.bx1[t], jy1=u.bb.by1[t], jx2=u.bb.bx2[t], jy2=u.bb.by2[t];
        float aj = (jx2-jx1)*(jy2-jy1);
        int ccx = min(31, max(0, (int)floorf((jx1+jx2)*0.5f*CELL_INV)));
        int ccy = min(31, max(0, (int)floorf((jy1+jy2)*0.5f*CELL_INV)));
        int gy0 = max(ccy-1,0), gy1 = min(ccy+1,31);
        int gx0 = max(ccx-1,0), gx1 = min(ccx+1,31);
        for (int gy = gy0; gy <= gy1; gy++)
        for (int gx = gx0; gx <= gx1; gx++) {
            int c = gy*32 + gx;
            int pe = u.bb.cstart[c+1];
            for (int p = u.bb.cstart[c]; p < pe; p++) {
                int i = u.bb.list[p];
                if (i >= t) continue;
                float xx1 = fmaxf(u.bb.bx1[i], jx1);
                float yy1 = fmaxf(u.bb.by1[i], jy1);
                float xx2 = fminf(u.bb.bx2[i], jx2);
                float yy2 = fminf(u.bb.by2[i], jy2);
                float iw2 = xx2 - xx1, ih2 = yy2 - yy1;
                if (iw2 <= 0.f || ih2 <= 0.f) continue;
                float inter = iw2 * ih2;
                float ai = (u.bb.bx2[i]-u.bb.bx1[i])*(u.bb.by2[i]-u.bb.by1[i]);
                float iou = inter / (ai + aj - inter + 1e-12f);
                if (iou > 0.5f) {
                    int e = atomicAdd(&sE, 1);
                    if (e < EMAX_) u.bb.edges[e] = ((unsigned)t << 16) | (unsigned)i;
                }
            }
        }
    }
    __syncthreads();

    // ---- B5: exact greedy resolve (edges sorted ascending by suppressed j) ----
    if (tid == 0) {
        int E = sE; if (E > EMAX_) E = EMAX_;
        for (int a = 1; a < E; a++) {
            unsigned v = u.bb.edges[a]; int q = a - 1;
            while (q >= 0 && u.bb.edges[q] > v) { u.bb.edges[q+1] = u.bb.edges[q]; q--; }
            u.bb.edges[q+1] = v;
        }
        for (int e = 0; e < E; e++) {
            int j = (int)(u.bb.edges[e] >> 16), i = (int)(u.bb.edges[e] & 0xffffu);
            if (u.bb.keep[i]) u.bb.keep[j] = 0;
        }
    }
    __syncthreads();

    // ---- B6: outputs: scores[B,K] ++ bboxes[B,K,4] ++ keep[B,K] ----
    const int so = 0, bo = B_*K_, ko = B_*K_*5;
    for (int t = tid; t < K_; t += 1024) {
        unsigned long long key = g_topk[b][t];
        float val = __uint_as_float((unsigned)(key >> 32));
        bool kp = u.bb.keep[t] != 0;
        int g = b*K_ + t;
        if (so + g < out_size) out[so + g] = kp ? val : 0.f;
        if (bo + g*4 + 3 < out_size) {
            float4 bx;
            bx.x = kp ? u.bb.bx1[t] : 0.f;
            bx.y = kp ? u.bb.by1[t] : 0.f;
            bx.z = kp ? u.bb.bx2[t] : 0.f;
            bx.w = kp ? u.bb.by2[t] : 0.f;
            *reinterpret_cast<float4*>(out + bo + g*4) = bx;
        }
        if (ko + g < out_size) out[ko + g] = kp ? 1.f : 0.f;
    }
}

// ---------------- launch ----------------
extern "C" void kernel_launch(void* const* d_in, const int* in_sizes, int n_in,
                              void* d_out, int out_size) {
    (void)in_sizes; (void)n_in;
    const float* scores = (const float*)d_in[0];
    const float* deltas = (const float*)d_in[1];
    const float* sizes  = (const float*)d_in[2];
    const int* p_stride = (const int*)d_in[3];
    const int* p_offy   = (const int*)d_in[4];
    const int* p_offx   = (const int*)d_in[5];

    dim3 g1(H_ / RPB_, B_);
    k_cand<<<g1, 256>>>(scores);
    k_post<<<B_, 1024>>>(deltas, sizes, p_stride, p_offy, p_offx,
                         (float*)d_out, out_size);
}

// round 12
// speedup vs baseline: 1.7217x; 1.7217x over previous
#include <cuda_runtime.h>
#include <cstdint>

#define B_ 8
#define H_ 1024
#define W_ 1024
#define HW_ (H_*W_)
#define K_ 2048
#define SURV_ 4096
#define NBIN_ 2048
#define NBUCK_ 128
#define CAPB_ 8192
#define NCELL_ 1024   /* 32x32 grid */
#define CELL_INV (1.0f/256.0f)
#define EMAX_ 512
#define RPB_ 16       /* rows per block in k_cand */
#define SBUF_ 2048    /* per-block candidate staging */
#define SPAN_ 3072    /* k_rank shared staging capacity */

// ---------------- scratch (static device memory only) ----------------
__device__ unsigned long long g_bcand[B_][NBUCK_][CAPB_];  // bucketed candidates
__device__ unsigned g_bcnt[B_][NBUCK_];                    // zeroed by k_sel each call
__device__ unsigned g_base[B_][NBIN_];    // seg start = #keys in higher bins
__device__ unsigned g_segend[B_][NBIN_];  // seg end   = #keys in bins >= bin
__device__ unsigned long long g_surv[B_][SURV_];
__device__ int g_m[B_];
__device__ unsigned long long g_topk[B_][K_];
__device__ float4 g_box[B_][K_];

// ---------------- K1: local-max candidates (paired separable max9, bucketed emit) ----------------
// block = 16 image rows (256 threads x 4 px), grid = (H/16, B)
__global__ void __launch_bounds__(256) k_cand(const float* __restrict__ sc) {
    const int b = blockIdx.y, h0 = blockIdx.x * RPB_;
    const int tid = threadIdx.x;
    const int w0 = tid * 4;
    const int lane = tid & 31;
    const float NI = -__int_as_float(0x7f800000); // -inf

    __shared__ int scnt;
    __shared__ unsigned long long sbuf[SBUF_];
    __shared__ unsigned scntb[NBUCK_];
    __shared__ unsigned sbase[NBUCK_];
    __shared__ unsigned scur[NBUCK_];
    if (tid < NBUCK_) { scntb[tid] = 0u; scur[tid] = 0u; }
    if (tid == 0) scnt = 0;
    __syncthreads();

    float v[6];
    float h3m[4], h3c[4], h3n[4], h3n2[4];
    float cenc[4], cenn[4], cenn2[4];

    #define LOADROW(hh) do {                                                \
        int _h = (hh);                                                      \
        if ((unsigned)_h >= (unsigned)H_) {                                 \
            v[0]=NI; v[1]=NI; v[2]=NI; v[3]=NI; v[4]=NI; v[5]=NI;           \
        } else {                                                            \
            const float* _r = sc + ((size_t)b * H_ + _h) * W_;              \
            float4 _m = *reinterpret_cast<const float4*>(_r + w0);          \
            float _lw = __shfl_up_sync(0xffffffffu, _m.w, 1);               \
            float _rx = __shfl_down_sync(0xffffffffu, _m.x, 1);             \
            v[1]=_m.x; v[2]=_m.y; v[3]=_m.z; v[4]=_m.w;                     \
            v[0] = lane        ? _lw : ((w0 > 0)      ? _r[w0-1] : NI);     \
            v[5] = (lane != 31)? _rx : ((w0 + 4 < W_) ? _r[w0+4] : NI);     \
        }                                                                   \
    } while (0)
    // horizontal 3-max with shared pair-maxes: 7 fmax / 4 px
    #define H3(d) do {                                                      \
        float _q0 = fmaxf(v[0], v[1]);                                      \
        float _q2 = fmaxf(v[2], v[3]);                                      \
        float _q4 = fmaxf(v[4], v[5]);                                      \
        d[0] = fmaxf(_q0, v[2]);                                            \
        d[1] = fmaxf(v[1], _q2);                                            \
        d[2] = fmaxf(_q2, v[4]);                                            \
        d[3] = fmaxf(v[3], _q4);                                            \
    } while (0)
    #define EMIT(s_, hh_, p_) do {                                          \
        int _pos = atomicAdd(&scnt, 1);                                     \
        if (_pos < SBUF_) {                                                 \
            unsigned _idx = (unsigned)((hh_) * W_ + w0 + (p_));             \
            unsigned _sb = __float_as_uint(s_);                             \
            sbuf[_pos] = ((unsigned long long)_sb << 32) | (unsigned)(~_idx);\
        }                                                                   \
    } while (0)

    LOADROW(h0 - 1); H3(h3m);
    LOADROW(h0);     H3(h3c); cenc[0]=v[1]; cenc[1]=v[2]; cenc[2]=v[3]; cenc[3]=v[4];

    #pragma unroll
    for (int r = 0; r < RPB_; r += 2) {
        LOADROW(h0 + r + 1); H3(h3n);  cenn[0]=v[1];  cenn[1]=v[2];  cenn[2]=v[3];  cenn[3]=v[4];
        LOADROW(h0 + r + 2); H3(h3n2); cenn2[0]=v[1]; cenn2[1]=v[2]; cenn2[2]=v[3]; cenn2[3]=v[4];
        #pragma unroll
        for (int p = 0; p < 4; p++) {
            float vp = fmaxf(h3c[p], h3n[p]);           // rows r, r+1 vertical pair
            float pool0 = fmaxf(h3m[p], vp);            // rows r-1..r+1
            float s0v = cenc[p];
            if (s0v > 0.5f && s0v == pool0) EMIT(s0v, h0 + r, p);
            float pool1 = fmaxf(vp, h3n2[p]);           // rows r..r+2
            float s1v = cenn[p];
            if (s1v > 0.5f && s1v == pool1) EMIT(s1v, h0 + r + 1, p);
        }
        #pragma unroll
        for (int q = 0; q < 4; q++) { h3m[q]=h3n[q]; h3c[q]=h3n2[q]; cenc[q]=cenn2[q]; }
    }
    __syncthreads();

    int c = scnt < SBUF_ ? scnt : SBUF_;
    // pass 0: per-bucket counts
    for (int i = tid; i < c; i += 256) {
        int bu = (int)((unsigned)(sbuf[i] >> 48) & (NBUCK_-1));
        atomicAdd(&scntb[bu], 1u);
    }
    __syncthreads();
    // reserve global ranges per non-empty bucket
    if (tid < NBUCK_) {
        unsigned cnt = scntb[tid];
        if (cnt) sbase[tid] = atomicAdd(&g_bcnt[b][tid], cnt);
    }
    __syncthreads();
    // pass 1: scatter to global buckets
    for (int i = tid; i < c; i += 256) {
        unsigned long long key = sbuf[i];
        int bu = (int)((unsigned)(key >> 48) & (NBUCK_-1));
        unsigned pos = atomicAdd(&scur[bu], 1u) + sbase[bu];
        if (pos < CAPB_) g_bcand[b][bu][pos] = key;
    }
    #undef LOADROW
    #undef H3
    #undef EMIT
}

// ---------------- K2: selection: coarse bucket -> fine hist -> threshold ->
//                    bases -> shared-cursor compaction (one CTA per batch) ----------------
__global__ void __launch_bounds__(1024) k_sel() {
    const int b = blockIdx.x, tid = threadIdx.x;
    __shared__ unsigned sfx[NBIN_];      // fine hist -> suffix sums -> cursors
    __shared__ unsigned sbcnt[NBUCK_];
    __shared__ int sB, sT;

    if (tid < NBUCK_) {
        unsigned cnt = g_bcnt[b][tid];
        sbcnt[tid] = cnt < CAPB_ ? cnt : CAPB_;
        g_bcnt[b][tid] = 0u;             // reset for next graph replay
    }
    sfx[tid] = 0u; sfx[tid + 1024] = 0u;
    if (tid == 0) sT = 0;
    __syncthreads();

    // coarse: largest bucket B* with (#keys in buckets >= B*) >= K
    if (tid == 0) {
        unsigned acc = 0; int Bst = 0;
        for (int bu = NBUCK_-1; bu >= 0; bu--) {
            acc += sbcnt[bu];
            if (acc >= K_) { Bst = bu; break; }
        }
        sB = Bst;
    }
    __syncthreads();
    const int Bst = sB;

    // fine histogram of keys in surviving buckets
    for (int bu = Bst; bu < NBUCK_; bu++) {
        int cnt = (int)sbcnt[bu];
        for (int i = tid; i < cnt; i += 1024) {
            unsigned long long key = g_bcand[b][bu][i];
            atomicAdd(&sfx[(unsigned)(key >> 44) & (NBIN_-1)], 1u);
        }
    }
    __syncthreads();

    // inclusive suffix sums: sfx[i] = #counted keys with bin >= i
    for (int off = 1; off < NBIN_; off <<= 1) {
        unsigned v0 = sfx[tid]      + ((tid + off        < NBIN_) ? sfx[tid + off]        : 0u);
        unsigned v1 = sfx[tid+1024] + ((tid + 1024 + off < NBIN_) ? sfx[tid + 1024 + off] : 0u);
        __syncthreads();
        sfx[tid] = v0; sfx[tid + 1024] = v1;
        __syncthreads();
    }

    // threshold bin T: largest bin with suffix >= K (stays 0 if total < K)
    for (int i = tid; i < NBIN_; i += 1024) {
        unsigned s = sfx[i];
        unsigned nx = (i + 1 < NBIN_) ? sfx[i+1] : 0u;
        if (s >= K_ && nx < K_) sT = i;
    }
    __syncthreads();
    const int T = sT;
    unsigned M = sfx[T]; if (M > SURV_) M = SURV_;

    // per-bin base/segend to gmem; then convert sfx to scatter cursors
    unsigned base0, base1;
    {
        unsigned s0 = sfx[tid],      n0 = (tid + 1 < NBIN_)        ? sfx[tid+1]      : 0u;
        unsigned s1 = sfx[tid+1024], n1 = (tid + 1024 + 1 < NBIN_) ? sfx[tid+1024+1] : 0u;
        g_base[b][tid] = n0;        g_segend[b][tid] = s0;
        g_base[b][tid+1024] = n1;   g_segend[b][tid+1024] = s1;
        base0 = n0; base1 = n1;
    }
    __syncthreads();
    sfx[tid] = base0; sfx[tid + 1024] = base1;
    __syncthreads();

    // compaction with shared cursors
    for (int bu = Bst; bu < NBUCK_; bu++) {
        int cnt = (int)sbcnt[bu];
        for (int i = tid; i < cnt; i += 1024) {
            unsigned long long key = g_bcand[b][bu][i];
            int bin = (int)((unsigned)(key >> 44) & (NBIN_-1));
            if (bin >= T) {
                unsigned pos = atomicAdd(&sfx[bin], 1u);
                if (pos < SURV_) g_surv[b][pos] = key;
            }
        }
    }

    // zero topk + publish M
    for (int i = tid; i < K_; i += 1024) g_topk[b][i] = 0ull;
    if (tid == 0) g_m[b] = (int)M;
}

// ---------------- K3: exact rank (shared-staged segments) + scatter + decode ----------------
// grid = (16, B), 256 threads; block covers surv slots [x*256, x*256+256)
__global__ void __launch_bounds__(256) k_rank(
    const float* __restrict__ deltas, const float* __restrict__ sizes,
    const int* __restrict__ p_stride, const int* __restrict__ p_offy,
    const int* __restrict__ p_offx)
{
    const int b = blockIdx.y, tid = threadIdx.x;
    const int p = blockIdx.x * 256 + tid;
    const int M = g_m[b];
    if (blockIdx.x * 256 >= M) return;

    __shared__ unsigned long long skey[SPAN_];
    __shared__ int slo, shi;
    if (tid == 0) { slo = SURV_; shi = 0; }
    __syncthreads();

    unsigned long long key = 0ull;
    int s0 = 0, e = 0;
    if (p < M) {
        key = g_surv[b][p];
        int bin = (int)((unsigned)(key >> 44) & (NBIN_-1));
        s0 = (int)g_base[b][bin];
        e  = (int)g_segend[b][bin];
        if (e > SURV_) e = SURV_;
        atomicMin(&slo, s0);
        atomicMax(&shi, e);
    }
    __syncthreads();
    const int lo = slo, hi = shi;
    const int span = hi - lo;
    int rank = s0;

    if (span <= SPAN_) {
        for (int i = tid; i < span; i += 256) skey[i] = g_surv[b][lo + i];
        __syncthreads();
        if (p < M) {
            const unsigned long long* seg = &skey[s0 - lo];
            const int n = e - s0;
            int c0 = 0, c1 = 0, c2 = 0, c3 = 0;
            int m = 0;
            for (; m + 4 <= n; m += 4) {
                c0 += (seg[m]   > key);
                c1 += (seg[m+1] > key);
                c2 += (seg[m+2] > key);
                c3 += (seg[m+3] > key);
            }
            for (; m < n; m++) c0 += (seg[m] > key);
            rank += c0 + c1 + c2 + c3;
        }
    } else if (p < M) {
        // fallback (should not happen in practice): scan segment from global
        const unsigned long long* seg = g_surv[b];
        int c0 = 0, c1 = 0, c2 = 0, c3 = 0;
        int m = s0;
        for (; m + 4 <= e; m += 4) {
            c0 += (seg[m]   > key);
            c1 += (seg[m+1] > key);
            c2 += (seg[m+2] > key);
            c3 += (seg[m+3] > key);
        }
        for (; m < e; m++) c0 += (seg[m] > key);
        rank += c0 + c1 + c2 + c3;
    }

    if (p < M && rank < K_) {
        g_topk[b][rank] = key;
        // decode box (exact reference op order)
        const int stride = *p_stride, offy = *p_offy, offx = *p_offx;
        unsigned idx = ~(unsigned)key;
        int iw = (int)(idx & (W_-1)), ih = (int)(idx >> 10);
        float dx = deltas[((size_t)b*2 + 0)*HW_ + idx];
        float dy = deltas[((size_t)b*2 + 1)*HW_ + idx];
        float sx = sizes [((size_t)b*2 + 0)*HW_ + idx];
        float sy = sizes [((size_t)b*2 + 1)*HW_ + idx];
        float cx = (float)(iw*stride + offx) + dx;
        float cy = (float)(ih*stride + offy) + dy;
        float4 box;
        box.x = cx - sx*0.5f; box.y = cy - sy*0.5f;
        box.z = cx + sx*0.5f; box.w = cy + sy*0.5f;
        g_box[b][rank] = box;
    }
}

// ---------------- K4: sparse-edge greedy NMS + outputs ----------------
__global__ void __launch_bounds__(1024) k_nms(float* __restrict__ out, int out_size)
{
    const int b = blockIdx.x, tid = threadIdx.x;
    __shared__ float bx1[K_], by1[K_], bx2[K_], by2[K_];   // 32 KB
    __shared__ unsigned cellcnt[NCELL_];
    __shared__ unsigned short cstart[NCELL_ + 2];
    __shared__ unsigned short list[K_];
    __shared__ unsigned short cellof[K_];
    __shared__ unsigned char keepA[K_];
    __shared__ unsigned edges[EMAX_];
    __shared__ unsigned wsum[32];
    __shared__ int sE;

    if (tid == 0) sE = 0;
    cellcnt[tid] = 0;
    __syncthreads();

    // load boxes (coalesced) + bin into cells
    for (int t = tid; t < K_; t += 1024) {
        unsigned long long key = g_topk[b][t];
        float4 box = g_box[b][t];
        bool valid = key != 0ull;
        if (!valid) { box.x=0.f; box.y=0.f; box.z=0.f; box.w=0.f; }
        bx1[t]=box.x; by1[t]=box.y; bx2[t]=box.z; by2[t]=box.w;
        keepA[t] = valid ? 1 : 0;
        unsigned short cell = 0;
        if (valid) {
            int ccx = min(31, max(0, (int)floorf((box.x+box.z)*0.5f*CELL_INV)));
            int ccy = min(31, max(0, (int)floorf((box.y+box.w)*0.5f*CELL_INV)));
            cell = (unsigned short)(ccy*32 + ccx);
            atomicAdd(&cellcnt[cell], 1u);
        }
        cellof[t] = cell;
    }
    __syncthreads();

    // exclusive scan over 1024 cells -> cstart; cellcnt becomes scatter cursor
    {
        unsigned orig = cellcnt[tid];
        unsigned x = orig;
        int lane = tid & 31, wid = tid >> 5;
        for (int o = 1; o < 32; o <<= 1) {
            unsigned y = __shfl_up_sync(0xffffffffu, x, o);
            if (lane >= o) x += y;
        }
        if (lane == 31) wsum[wid] = x;
        __syncthreads();
        if (wid == 0) {
            unsigned s2 = wsum[lane];
            for (int o = 1; o < 32; o <<= 1) {
                unsigned y = __shfl_up_sync(0xffffffffu, s2, o);
                if (lane >= o) s2 += y;
            }
            wsum[lane] = s2;
        }
        __syncthreads();
        unsigned incl = x + (wid > 0 ? wsum[wid-1] : 0u);
        unsigned excl = incl - orig;
        cstart[tid] = (unsigned short)excl;
        if (tid == NCELL_-1) cstart[NCELL_] = (unsigned short)incl;
        __syncthreads();
        cellcnt[tid] = excl;
    }
    __syncthreads();

    // scatter boxes into cell-sorted list
    for (int t = tid; t < K_; t += 1024) {
        if (keepA[t]) {
            unsigned p = atomicAdd(&cellcnt[cellof[t]], 1u);
            list[p] = (unsigned short)t;
        }
    }
    __syncthreads();

    // sparse edge detection: pairs (i<j) with IoU > 0.5 via 3x3 cell neighborhood
    for (int t = tid; t < K_; t += 1024) {
        if (!keepA[t]) continue;
        float jx1=bx1[t], jy1=by1[t], jx2=bx2[t], jy2=by2[t];
        float aj = (jx2-jx1)*(jy2-jy1);
        int cc = cellof[t];
        int ccx = cc & 31, ccy = cc >> 5;
        int gy0 = max(ccy-1,0), gy1 = min(ccy+1,31);
        int gx0 = max(ccx-1,0), gx1 = min(ccx+1,31);
        for (int gy = gy0; gy <= gy1; gy++)
        for (int gx = gx0; gx <= gx1; gx++) {
            int c = gy*32 + gx;
            int pe = cstart[c+1];
            for (int p = cstart[c]; p < pe; p++) {
                int i = list[p];
                if (i >= t) continue;
                float xx1 = fmaxf(bx1[i], jx1);
                float yy1 = fmaxf(by1[i], jy1);
                float xx2 = fminf(bx2[i], jx2);
                float yy2 = fminf(by2[i], jy2);
                float iw2 = xx2 - xx1, ih2 = yy2 - yy1;
                if (iw2 <= 0.f || ih2 <= 0.f) continue;
                float inter = iw2 * ih2;
                float ai = (bx2[i]-bx1[i])*(by2[i]-by1[i]);
                float iou = inter / (ai + aj - inter + 1e-12f);
                if (iou > 0.5f) {
                    int e = atomicAdd(&sE, 1);
                    if (e < EMAX_) edges[e] = ((unsigned)t << 16) | (unsigned)i;
                }
            }
        }
    }
    __syncthreads();

    // exact greedy resolve: edges sorted ascending by suppressed index j
    if (tid == 0) {
        int E = sE; if (E > EMAX_) E = EMAX_;
        for (int a = 1; a < E; a++) {
            unsigned v = edges[a]; int q = a - 1;
            while (q >= 0 && edges[q] > v) { edges[q+1] = edges[q]; q--; }
            edges[q+1] = v;
        }
        for (int e = 0; e < E; e++) {
            int j = (int)(edges[e] >> 16), i = (int)(edges[e] & 0xffffu);
            if (keepA[i]) keepA[j] = 0;
        }
    }
    __syncthreads();

    // outputs: scores[B,K] ++ bboxes[B,K,4] ++ keep[B,K]
    const int so = 0, bo = B_*K_, ko = B_*K_*5;
    for (int t = tid; t < K_; t += 1024) {
        unsigned long long key = g_topk[b][t];
        float val = __uint_as_float((unsigned)(key >> 32));
        bool kp = keepA[t] != 0;
        int g = b*K_ + t;
        if (so + g < out_size) out[so + g] = kp ? val : 0.f;
        if (bo + g*4 + 3 < out_size) {
            float4 bx;
            bx.x = kp ? bx1[t] : 0.f;
            bx.y = kp ? by1[t] : 0.f;
            bx.z = kp ? bx2[t] : 0.f;
            bx.w = kp ? by2[t] : 0.f;
            *reinterpret_cast<float4*>(out + bo + g*4) = bx;
        }
        if (ko + g < out_size) out[ko + g] = kp ? 1.f : 0.f;
    }
}

// ---------------- launch ----------------
extern "C" void kernel_launch(void* const* d_in, const int* in_sizes, int n_in,
                              void* d_out, int out_size) {
    (void)in_sizes; (void)n_in;
    const float* scores = (const float*)d_in[0];
    const float* deltas = (const float*)d_in[1];
    const float* sizes  = (const float*)d_in[2];
    const int* p_stride = (const int*)d_in[3];
    const int* p_offy   = (const int*)d_in[4];
    const int* p_offx   = (const int*)d_in[5];

    dim3 g1(H_ / RPB_, B_);
    k_cand<<<g1, 256>>>(scores);
    k_sel<<<B_, 1024>>>();
    dim3 gr(SURV_ / 256, B_);
    k_rank<<<gr, 256>>>(deltas, sizes, p_stride, p_offy, p_offx);
    k_nms<<<B_, 1024>>>((float*)d_out, out_size);
}

// round 13
// speedup vs baseline: 1.7826x; 1.0354x over previous
#include <cuda_runtime.h>
#include <cstdint>

#define B_ 8
#define H_ 1024
#define W_ 1024
#define HW_ (H_*W_)
#define K_ 2048
#define SURV_ 4096
#define NBIN_ 2048
#define NBUCK_ 128
#define CAPB_ 8192
#define NCELL_ 1024   /* 32x32 grid */
#define CELL_INV (1.0f/256.0f)
#define EMAX_ 512
#define RPB_ 16       /* rows per block in k_cand */
#define SBUF_ 2048    /* per-block candidate staging */
#define SPAN_ 3072    /* k_rank shared staging capacity */

// ---------------- scratch (static device memory only) ----------------
__device__ unsigned long long g_bcand[B_][NBUCK_][CAPB_];  // bucketed candidates
__device__ unsigned g_bcnt[B_][NBUCK_];                    // zeroed by k_sel each call
__device__ unsigned g_base[B_][NBIN_];    // seg start = #keys in higher bins
__device__ unsigned g_segend[B_][NBIN_];  // seg end   = #keys in bins >= bin
__device__ unsigned long long g_surv[B_][SURV_];
__device__ int g_m[B_];
__device__ unsigned long long g_topk[B_][K_];
__device__ float4 g_box[B_][K_];
__device__ unsigned short g_cellof[B_][K_];
__device__ unsigned short g_cstart[B_][NCELL_ + 1];
__device__ unsigned short g_list[B_][K_];
__device__ unsigned g_edges[B_][EMAX_];
__device__ int g_ne[B_];

// ---------------- K1: local-max candidates (paired separable max9, bucketed emit) ----------------
// block = 16 image rows (256 threads x 4 px), grid = (H/16, B)
__global__ void __launch_bounds__(256) k_cand(const float* __restrict__ sc) {
    const int b = blockIdx.y, h0 = blockIdx.x * RPB_;
    const int tid = threadIdx.x;
    const int w0 = tid * 4;
    const int lane = tid & 31;
    const float NI = -__int_as_float(0x7f800000); // -inf

    __shared__ int scnt;
    __shared__ unsigned long long sbuf[SBUF_];
    __shared__ unsigned scntb[NBUCK_];
    __shared__ unsigned sbase[NBUCK_];
    __shared__ unsigned scur[NBUCK_];
    if (tid < NBUCK_) { scntb[tid] = 0u; scur[tid] = 0u; }
    if (tid == 0) scnt = 0;
    __syncthreads();

    float v[6];
    float h3m[4], h3c[4], h3n[4], h3n2[4];
    float cenc[4], cenn[4], cenn2[4];

    #define LOADROW(hh) do {                                                \
        int _h = (hh);                                                      \
        if ((unsigned)_h >= (unsigned)H_) {                                 \
            v[0]=NI; v[1]=NI; v[2]=NI; v[3]=NI; v[4]=NI; v[5]=NI;           \
        } else {                                                            \
            const float* _r = sc + ((size_t)b * H_ + _h) * W_;              \
            float4 _m = *reinterpret_cast<const float4*>(_r + w0);          \
            float _lw = __shfl_up_sync(0xffffffffu, _m.w, 1);               \
            float _rx = __shfl_down_sync(0xffffffffu, _m.x, 1);             \
            v[1]=_m.x; v[2]=_m.y; v[3]=_m.z; v[4]=_m.w;                     \
            v[0] = lane        ? _lw : ((w0 > 0)      ? _r[w0-1] : NI);     \
            v[5] = (lane != 31)? _rx : ((w0 + 4 < W_) ? _r[w0+4] : NI);     \
        }                                                                   \
    } while (0)
    // horizontal 3-max with shared pair-maxes: 7 fmax / 4 px
    #define H3(d) do {                                                      \
        float _q0 = fmaxf(v[0], v[1]);                                      \
        float _q2 = fmaxf(v[2], v[3]);                                      \
        float _q4 = fmaxf(v[4], v[5]);                                      \
        d[0] = fmaxf(_q0, v[2]);                                            \
        d[1] = fmaxf(v[1], _q2);                                            \
        d[2] = fmaxf(_q2, v[4]);                                            \
        d[3] = fmaxf(v[3], _q4);                                            \
    } while (0)
    #define EMIT(s_, hh_, p_) do {                                          \
        int _pos = atomicAdd(&scnt, 1);                                     \
        if (_pos < SBUF_) {                                                 \
            unsigned _idx = (unsigned)((hh_) * W_ + w0 + (p_));             \
            unsigned _sb = __float_as_uint(s_);                             \
            sbuf[_pos] = ((unsigned long long)_sb << 32) | (unsigned)(~_idx);\
        }                                                                   \
    } while (0)

    LOADROW(h0 - 1); H3(h3m);
    LOADROW(h0);     H3(h3c); cenc[0]=v[1]; cenc[1]=v[2]; cenc[2]=v[3]; cenc[3]=v[4];

    #pragma unroll
    for (int r = 0; r < RPB_; r += 2) {
        LOADROW(h0 + r + 1); H3(h3n);  cenn[0]=v[1];  cenn[1]=v[2];  cenn[2]=v[3];  cenn[3]=v[4];
        LOADROW(h0 + r + 2); H3(h3n2); cenn2[0]=v[1]; cenn2[1]=v[2]; cenn2[2]=v[3]; cenn2[3]=v[4];
        #pragma unroll
        for (int p = 0; p < 4; p++) {
            float vp = fmaxf(h3c[p], h3n[p]);           // rows r, r+1 vertical pair
            float pool0 = fmaxf(h3m[p], vp);            // rows r-1..r+1
            float s0v = cenc[p];
            if (s0v > 0.5f && s0v == pool0) EMIT(s0v, h0 + r, p);
            float pool1 = fmaxf(vp, h3n2[p]);           // rows r..r+2
            float s1v = cenn[p];
            if (s1v > 0.5f && s1v == pool1) EMIT(s1v, h0 + r + 1, p);
        }
        #pragma unroll
        for (int q = 0; q < 4; q++) { h3m[q]=h3n[q]; h3c[q]=h3n2[q]; cenc[q]=cenn2[q]; }
    }
    __syncthreads();

    int c = scnt < SBUF_ ? scnt : SBUF_;
    // pass 0: per-bucket counts
    for (int i = tid; i < c; i += 256) {
        int bu = (int)((unsigned)(sbuf[i] >> 48) & (NBUCK_-1));
        atomicAdd(&scntb[bu], 1u);
    }
    __syncthreads();
    // reserve global ranges per non-empty bucket
    if (tid < NBUCK_) {
        unsigned cnt = scntb[tid];
        if (cnt) sbase[tid] = atomicAdd(&g_bcnt[b][tid], cnt);
    }
    __syncthreads();
    // pass 1: scatter to global buckets
    for (int i = tid; i < c; i += 256) {
        unsigned long long key = sbuf[i];
        int bu = (int)((unsigned)(key >> 48) & (NBUCK_-1));
        unsigned pos = atomicAdd(&scur[bu], 1u) + sbase[bu];
        if (pos < CAPB_) g_bcand[b][bu][pos] = key;
    }
    #undef LOADROW
    #undef H3
    #undef EMIT
}

// ---------------- K2: selection: coarse bucket -> fine hist -> threshold ->
//                    bases -> shared-cursor compaction (one CTA per batch) ----------------
__global__ void __launch_bounds__(1024) k_sel() {
    const int b = blockIdx.x, tid = threadIdx.x;
    __shared__ unsigned sfx[NBIN_];      // fine hist -> suffix sums -> cursors
    __shared__ unsigned sbcnt[NBUCK_];
    __shared__ int sB, sT;

    if (tid < NBUCK_) {
        unsigned cnt = g_bcnt[b][tid];
        sbcnt[tid] = cnt < CAPB_ ? cnt : CAPB_;
        g_bcnt[b][tid] = 0u;             // reset for next graph replay
    }
    sfx[tid] = 0u; sfx[tid + 1024] = 0u;
    if (tid == 0) { sT = 0; g_ne[b] = 0; }
    __syncthreads();

    // coarse: largest bucket B* with (#keys in buckets >= B*) >= K
    if (tid == 0) {
        unsigned acc = 0; int Bst = 0;
        for (int bu = NBUCK_-1; bu >= 0; bu--) {
            acc += sbcnt[bu];
            if (acc >= K_) { Bst = bu; break; }
        }
        sB = Bst;
    }
    __syncthreads();
    const int Bst = sB;

    // fine histogram of keys in surviving buckets
    for (int bu = Bst; bu < NBUCK_; bu++) {
        int cnt = (int)sbcnt[bu];
        for (int i = tid; i < cnt; i += 1024) {
            unsigned long long key = g_bcand[b][bu][i];
            atomicAdd(&sfx[(unsigned)(key >> 44) & (NBIN_-1)], 1u);
        }
    }
    __syncthreads();

    // inclusive suffix sums: sfx[i] = #counted keys with bin >= i
    for (int off = 1; off < NBIN_; off <<= 1) {
        unsigned v0 = sfx[tid]      + ((tid + off        < NBIN_) ? sfx[tid + off]        : 0u);
        unsigned v1 = sfx[tid+1024] + ((tid + 1024 + off < NBIN_) ? sfx[tid + 1024 + off] : 0u);
        __syncthreads();
        sfx[tid] = v0; sfx[tid + 1024] = v1;
        __syncthreads();
    }

    // threshold bin T: largest bin with suffix >= K (stays 0 if total < K)
    for (int i = tid; i < NBIN_; i += 1024) {
        unsigned s = sfx[i];
        unsigned nx = (i + 1 < NBIN_) ? sfx[i+1] : 0u;
        if (s >= K_ && nx < K_) sT = i;
    }
    __syncthreads();
    const int T = sT;
    unsigned M = sfx[T]; if (M > SURV_) M = SURV_;

    // per-bin base/segend to gmem; then convert sfx to scatter cursors
    unsigned base0, base1;
    {
        unsigned s0 = sfx[tid],      n0 = (tid + 1 < NBIN_)        ? sfx[tid+1]      : 0u;
        unsigned s1 = sfx[tid+1024], n1 = (tid + 1024 + 1 < NBIN_) ? sfx[tid+1024+1] : 0u;
        g_base[b][tid] = n0;        g_segend[b][tid] = s0;
        g_base[b][tid+1024] = n1;   g_segend[b][tid+1024] = s1;
        base0 = n0; base1 = n1;
    }
    __syncthreads();
    sfx[tid] = base0; sfx[tid + 1024] = base1;
    __syncthreads();

    // compaction with shared cursors
    for (int bu = Bst; bu < NBUCK_; bu++) {
        int cnt = (int)sbcnt[bu];
        for (int i = tid; i < cnt; i += 1024) {
            unsigned long long key = g_bcand[b][bu][i];
            int bin = (int)((unsigned)(key >> 44) & (NBIN_-1));
            if (bin >= T) {
                unsigned pos = atomicAdd(&sfx[bin], 1u);
                if (pos < SURV_) g_surv[b][pos] = key;
            }
        }
    }

    // zero topk + publish M
    for (int i = tid; i < K_; i += 1024) g_topk[b][i] = 0ull;
    if (tid == 0) g_m[b] = (int)M;
}

// ---------------- K3: exact rank (shared-staged segments) + scatter + decode ----------------
// grid = (16, B), 256 threads; block covers surv slots [x*256, x*256+256)
__global__ void __launch_bounds__(256) k_rank(
    const float* __restrict__ deltas, const float* __restrict__ sizes,
    const int* __restrict__ p_stride, const int* __restrict__ p_offy,
    const int* __restrict__ p_offx)
{
    const int b = blockIdx.y, tid = threadIdx.x;
    const int p = blockIdx.x * 256 + tid;
    const int M = g_m[b];
    if (blockIdx.x * 256 >= M) return;

    __shared__ unsigned long long skey[SPAN_];
    __shared__ int slo, shi;
    if (tid == 0) { slo = SURV_; shi = 0; }
    __syncthreads();

    unsigned long long key = 0ull;
    int s0 = 0, e = 0;
    if (p < M) {
        key = g_surv[b][p];
        int bin = (int)((unsigned)(key >> 44) & (NBIN_-1));
        s0 = (int)g_base[b][bin];
        e  = (int)g_segend[b][bin];
        if (e > SURV_) e = SURV_;
        atomicMin(&slo, s0);
        atomicMax(&shi, e);
    }
    __syncthreads();
    const int lo = slo, hi = shi;
    const int span = hi - lo;
    int rank = s0;

    if (span <= SPAN_) {
        for (int i = tid; i < span; i += 256) skey[i] = g_surv[b][lo + i];
        __syncthreads();
        if (p < M) {
            const unsigned long long* seg = &skey[s0 - lo];
            const int n = e - s0;
            int c0 = 0, c1 = 0, c2 = 0, c3 = 0;
            int m = 0;
            for (; m + 4 <= n; m += 4) {
                c0 += (seg[m]   > key);
                c1 += (seg[m+1] > key);
                c2 += (seg[m+2] > key);
                c3 += (seg[m+3] > key);
            }
            for (; m < n; m++) c0 += (seg[m] > key);
            rank += c0 + c1 + c2 + c3;
        }
    } else if (p < M) {
        // fallback: scan segment from global
        const unsigned long long* seg = g_surv[b];
        int c0 = 0, c1 = 0, c2 = 0, c3 = 0;
        int m = s0;
        for (; m + 4 <= e; m += 4) {
            c0 += (seg[m]   > key);
            c1 += (seg[m+1] > key);
            c2 += (seg[m+2] > key);
            c3 += (seg[m+3] > key);
        }
        for (; m < e; m++) c0 += (seg[m] > key);
        rank += c0 + c1 + c2 + c3;
    }

    if (p < M && rank < K_) {
        g_topk[b][rank] = key;
        // decode box (exact reference op order)
        const int stride = *p_stride, offy = *p_offy, offx = *p_offx;
        unsigned idx = ~(unsigned)key;
        int iw = (int)(idx & (W_-1)), ih = (int)(idx >> 10);
        float dx = deltas[((size_t)b*2 + 0)*HW_ + idx];
        float dy = deltas[((size_t)b*2 + 1)*HW_ + idx];
        float sx = sizes [((size_t)b*2 + 0)*HW_ + idx];
        float sy = sizes [((size_t)b*2 + 1)*HW_ + idx];
        float cx = (float)(iw*stride + offx) + dx;
        float cy = (float)(ih*stride + offy) + dy;
        float4 box;
        box.x = cx - sx*0.5f; box.y = cy - sy*0.5f;
        box.z = cx + sx*0.5f; box.w = cy + sy*0.5f;
        g_box[b][rank] = box;
    }
}

// ---------------- K4: cell binning (count -> scan -> scatter), one CTA/batch ----------------
__global__ void __launch_bounds__(1024) k_bin() {
    const int b = blockIdx.x, tid = threadIdx.x;
    const int lane = tid & 31, wid = tid >> 5;
    __shared__ unsigned cellcnt[NCELL_];
    __shared__ unsigned wsum[32];
    cellcnt[tid] = 0u;
    __syncthreads();

    unsigned short cel[2]; bool val[2];
    #pragma unroll
    for (int k = 0; k < 2; k++) {
        int t = tid + k * 1024;
        unsigned long long key = g_topk[b][t];
        val[k] = key != 0ull;
        unsigned short cell = 0;
        if (val[k]) {
            float4 box = g_box[b][t];
            int ccx = min(31, max(0, (int)floorf((box.x+box.z)*0.5f*CELL_INV)));
            int ccy = min(31, max(0, (int)floorf((box.y+box.w)*0.5f*CELL_INV)));
            cell = (unsigned short)(ccy*32 + ccx);
            atomicAdd(&cellcnt[cell], 1u);
        }
        cel[k] = cell;
        g_cellof[b][t] = cell;
    }
    __syncthreads();

    // exclusive scan over 1024 cells
    unsigned orig = cellcnt[tid];
    unsigned x = orig;
    for (int o = 1; o < 32; o <<= 1) {
        unsigned y = __shfl_up_sync(0xffffffffu, x, o);
        if (lane >= o) x += y;
    }
    if (lane == 31) wsum[wid] = x;
    __syncthreads();
    if (wid == 0) {
        unsigned s2 = wsum[lane];
        for (int o = 1; o < 32; o <<= 1) {
            unsigned y = __shfl_up_sync(0xffffffffu, s2, o);
            if (lane >= o) s2 += y;
        }
        wsum[lane] = s2;
    }
    __syncthreads();
    unsigned incl = x + (wid > 0 ? wsum[wid-1] : 0u);
    unsigned excl = incl - orig;
    g_cstart[b][tid] = (unsigned short)excl;
    if (tid == NCELL_-1) g_cstart[b][NCELL_] = (unsigned short)incl;
    __syncthreads();
    cellcnt[tid] = excl;     // scatter cursors
    __syncthreads();

    #pragma unroll
    for (int k = 0; k < 2; k++) {
        if (val[k]) {
            unsigned p = atomicAdd(&cellcnt[cel[k]], 1u);
            g_list[b][p] = (unsigned short)(tid + k * 1024);
        }
    }
}

// ---------------- K5: chip-wide sparse edge detection ----------------
// grid = (8, B), 256 threads, 1 thread per box
__global__ void __launch_bounds__(256) k_edges() {
    const int b = blockIdx.y;
    const int t = blockIdx.x * 256 + threadIdx.x;
    unsigned long long key = g_topk[b][t];
    if (key == 0ull) return;
    float4 bj = g_box[b][t];
    float aj = (bj.z - bj.x) * (bj.w - bj.y);
    int cc = g_cellof[b][t];
    int ccx = cc & 31, ccy = cc >> 5;
    int gy0 = max(ccy-1,0), gy1 = min(ccy+1,31);
    int gx0 = max(ccx-1,0), gx1 = min(ccx+1,31);
    for (int gy = gy0; gy <= gy1; gy++)
    for (int gx = gx0; gx <= gx1; gx++) {
        int c = gy*32 + gx;
        int ps = g_cstart[b][c], pe = g_cstart[b][c+1];
        for (int p = ps; p < pe; p++) {
            int i = g_list[b][p];
            if (i >= t) continue;
            float4 bi = g_box[b][i];
            float xx1 = fmaxf(bi.x, bj.x);
            float yy1 = fmaxf(bi.y, bj.y);
            float xx2 = fminf(bi.z, bj.z);
            float yy2 = fminf(bi.w, bj.w);
            float iw2 = xx2 - xx1, ih2 = yy2 - yy1;
            if (iw2 <= 0.f || ih2 <= 0.f) continue;
            float inter = iw2 * ih2;
            float ai = (bi.z - bi.x) * (bi.w - bi.y);
            float iou = inter / (ai + aj - inter + 1e-12f);
            if (iou > 0.5f) {
                int e = atomicAdd(&g_ne[b], 1);
                if (e < EMAX_) g_edges[b][e] = ((unsigned)t << 16) | (unsigned)i;
            }
        }
    }
}

// ---------------- K6: greedy resolve + outputs, one CTA/batch ----------------
__global__ void __launch_bounds__(1024) k_final(float* __restrict__ out, int out_size) {
    const int b = blockIdx.x, tid = threadIdx.x;
    __shared__ unsigned edges[EMAX_];
    __shared__ unsigned char keep[K_];

    int E = g_ne[b]; if (E > EMAX_) E = EMAX_;
    for (int i = tid; i < E; i += 1024) edges[i] = g_edges[b][i];
    #pragma unroll
    for (int k = 0; k < 2; k++) {
        int t = tid + k * 1024;
        keep[t] = (g_topk[b][t] != 0ull) ? 1 : 0;
    }
    __syncthreads();

    // exact greedy resolve: edges sorted ascending by suppressed index j
    if (tid == 0) {
        for (int a = 1; a < E; a++) {
            unsigned v = edges[a]; int q = a - 1;
            while (q >= 0 && edges[q] > v) { edges[q+1] = edges[q]; q--; }
            edges[q+1] = v;
        }
        for (int e = 0; e < E; e++) {
            int j = (int)(edges[e] >> 16), i = (int)(edges[e] & 0xffffu);
            if (keep[i]) keep[j] = 0;
        }
    }
    __syncthreads();

    // outputs: scores[B,K] ++ bboxes[B,K,4] ++ keep[B,K]
    const int so = 0, bo = B_*K_, ko = B_*K_*5;
    #pragma unroll
    for (int k = 0; k < 2; k++) {
        int t = tid + k * 1024;
        unsigned long long key = g_topk[b][t];
        float val = __uint_as_float((unsigned)(key >> 32));
        bool kp = keep[t] != 0;
        float4 box = g_box[b][t];
        int g = b*K_ + t;
        if (so + g < out_size) out[so + g] = kp ? val : 0.f;
        if (bo + g*4 + 3 < out_size) {
            float4 bx;
            bx.x = kp ? box.x : 0.f;
            bx.y = kp ? box.y : 0.f;
            bx.z = kp ? box.z : 0.f;
            bx.w = kp ? box.w : 0.f;
            *reinterpret_cast<float4*>(out + bo + g*4) = bx;
        }
        if (ko + g < out_size) out[ko + g] = kp ? 1.f : 0.f;
    }
}

// ---------------- launch ----------------
extern "C" void kernel_launch(void* const* d_in, const int* in_sizes, int n_in,
                              void* d_out, int out_size) {
    (void)in_sizes; (void)n_in;
    const float* scores = (const float*)d_in[0];
    const float* deltas = (const float*)d_in[1];
    const float* sizes  = (const float*)d_in[2];
    const int* p_stride = (const int*)d_in[3];
    const int* p_offy   = (const int*)d_in[4];
    const int* p_offx   = (const int*)d_in[5];

    dim3 g1(H_ / RPB_, B_);
    k_cand<<<g1, 256>>>(scores);
    k_sel<<<B_, 1024>>>();
    dim3 gr(SURV_ / 256, B_);
    k_rank<<<gr, 256>>>(deltas, sizes, p_stride, p_offy, p_offx);
    k_bin<<<B_, 1024>>>();
    dim3 ge(K_ / 256, B_);
    k_edges<<<ge, 256>>>();
    k_final<<<B_, 1024>>>((float*)d_out, out_size);
}

// round 14
// speedup vs baseline: 1.7836x; 1.0006x over previous
#include <cuda_runtime.h>
#include <cstdint>

#define B_ 8
#define H_ 1024
#define W_ 1024
#define HW_ (H_*W_)
#define K_ 2048
#define SURV_ 4096
#define NBIN_ 2048
#define NBUCK_ 128
#define CAPB_ 8192
#define NCELL_ 1024   /* 32x32 grid */
#define CELL_INV (1.0f/256.0f)
#define EMAX_ 512
#define RPB_ 16       /* rows per block in k_cand */
#define SBUF_ 2048    /* per-block candidate staging */
#define SPAN_ 3072    /* k_rank shared staging capacity */

#if defined(__CUDA_ARCH__) && (__CUDA_ARCH__ >= 900)
#define GRID_SYNC()  cudaGridDependencySynchronize()
#define GRID_TRIG()  cudaTriggerProgrammaticLaunchCompletion()
#else
#define GRID_SYNC()
#define GRID_TRIG()
#endif

// ---------------- scratch (static device memory only) ----------------
__device__ unsigned long long g_bcand[B_][NBUCK_][CAPB_];  // bucketed candidates
__device__ unsigned g_bcnt[B_][NBUCK_];                    // zeroed by k_sel each call
__device__ unsigned g_base[B_][NBIN_];    // seg start = #keys in higher bins
__device__ unsigned g_segend[B_][NBIN_];  // seg end   = #keys in bins >= bin
__device__ unsigned long long g_surv[B_][SURV_];
__device__ int g_m[B_];
__device__ unsigned long long g_topk[B_][K_];
__device__ float4 g_box[B_][K_];
__device__ unsigned g_cellcnt[B_][NCELL_];   // zeroed by k_sel, filled by k_rank
__device__ unsigned short g_cellof[B_][K_];
__device__ unsigned short g_cstart[B_][NCELL_ + 1];
__device__ unsigned short g_list[B_][K_];
__device__ unsigned g_edges[B_][EMAX_];
__device__ int g_ne[B_];

// ---------------- K1: local-max candidates (paired separable max9, bucketed emit) ----------------
// block = 16 image rows (256 threads x 4 px), grid = (H/16, B)
__global__ void __launch_bounds__(256) k_cand(const float* __restrict__ sc) {
    const int b = blockIdx.y, h0 = blockIdx.x * RPB_;
    const int tid = threadIdx.x;
    const int w0 = tid * 4;
    const int lane = tid & 31;
    const float NI = -__int_as_float(0x7f800000); // -inf

    __shared__ int scnt;
    __shared__ unsigned long long sbuf[SBUF_];
    __shared__ unsigned scntb[NBUCK_];
    __shared__ unsigned sbase[NBUCK_];
    __shared__ unsigned scur[NBUCK_];
    if (tid < NBUCK_) { scntb[tid] = 0u; scur[tid] = 0u; }
    if (tid == 0) scnt = 0;
    __syncthreads();

    float v[6];
    float h3m[4], h3c[4], h3n[4], h3n2[4];
    float cenc[4], cenn[4], cenn2[4];

    #define LOADROW(hh) do {                                                \
        int _h = (hh);                                                      \
        if ((unsigned)_h >= (unsigned)H_) {                                 \
            v[0]=NI; v[1]=NI; v[2]=NI; v[3]=NI; v[4]=NI; v[5]=NI;           \
        } else {                                                            \
            const float* _r = sc + ((size_t)b * H_ + _h) * W_;              \
            float4 _m = *reinterpret_cast<const float4*>(_r + w0);          \
            float _lw = __shfl_up_sync(0xffffffffu, _m.w, 1);               \
            float _rx = __shfl_down_sync(0xffffffffu, _m.x, 1);             \
            v[1]=_m.x; v[2]=_m.y; v[3]=_m.z; v[4]=_m.w;                     \
            v[0] = lane        ? _lw : ((w0 > 0)      ? _r[w0-1] : NI);     \
            v[5] = (lane != 31)? _rx : ((w0 + 4 < W_) ? _r[w0+4] : NI);     \
        }                                                                   \
    } while (0)
    // horizontal 3-max with shared pair-maxes: 7 fmax / 4 px
    #define H3(d) do {                                                      \
        float _q0 = fmaxf(v[0], v[1]);                                      \
        float _q2 = fmaxf(v[2], v[3]);                                      \
        float _q4 = fmaxf(v[4], v[5]);                                      \
        d[0] = fmaxf(_q0, v[2]);                                            \
        d[1] = fmaxf(v[1], _q2);                                            \
        d[2] = fmaxf(_q2, v[4]);                                            \
        d[3] = fmaxf(v[3], _q4);                                            \
    } while (0)
    #define EMIT(s_, hh_, p_) do {                                          \
        int _pos = atomicAdd(&scnt, 1);                                     \
        if (_pos < SBUF_) {                                                 \
            unsigned _idx = (unsigned)((hh_) * W_ + w0 + (p_));             \
            unsigned _sb = __float_as_uint(s_);                             \
            sbuf[_pos] = ((unsigned long long)_sb << 32) | (unsigned)(~_idx);\
        }                                                                   \
    } while (0)

    LOADROW(h0 - 1); H3(h3m);
    LOADROW(h0);     H3(h3c); cenc[0]=v[1]; cenc[1]=v[2]; cenc[2]=v[3]; cenc[3]=v[4];

    #pragma unroll
    for (int r = 0; r < RPB_; r += 2) {
        LOADROW(h0 + r + 1); H3(h3n);  cenn[0]=v[1];  cenn[1]=v[2];  cenn[2]=v[3];  cenn[3]=v[4];
        LOADROW(h0 + r + 2); H3(h3n2); cenn2[0]=v[1]; cenn2[1]=v[2]; cenn2[2]=v[3]; cenn2[3]=v[4];
        #pragma unroll
        for (int p = 0; p < 4; p++) {
            float vp = fmaxf(h3c[p], h3n[p]);           // rows r, r+1 vertical pair
            float pool0 = fmaxf(h3m[p], vp);            // rows r-1..r+1
            float s0v = cenc[p];
            if (s0v > 0.5f && s0v == pool0) EMIT(s0v, h0 + r, p);
            float pool1 = fmaxf(vp, h3n2[p]);           // rows r..r+2
            float s1v = cenn[p];
            if (s1v > 0.5f && s1v == pool1) EMIT(s1v, h0 + r + 1, p);
        }
        #pragma unroll
        for (int q = 0; q < 4; q++) { h3m[q]=h3n[q]; h3c[q]=h3n2[q]; cenc[q]=cenn2[q]; }
    }
    __syncthreads();

    int c = scnt < SBUF_ ? scnt : SBUF_;
    // pass 0: per-bucket counts
    for (int i = tid; i < c; i += 256) {
        int bu = (int)((unsigned)(sbuf[i] >> 48) & (NBUCK_-1));
        atomicAdd(&scntb[bu], 1u);
    }
    __syncthreads();
    // reserve global ranges per non-empty bucket
    if (tid < NBUCK_) {
        unsigned cnt = scntb[tid];
        if (cnt) sbase[tid] = atomicAdd(&g_bcnt[b][tid], cnt);
    }
    __syncthreads();
    // pass 1: scatter to global buckets
    for (int i = tid; i < c; i += 256) {
        unsigned long long key = sbuf[i];
        int bu = (int)((unsigned)(key >> 48) & (NBUCK_-1));
        unsigned pos = atomicAdd(&scur[bu], 1u) + sbase[bu];
        if (pos < CAPB_) g_bcand[b][bu][pos] = key;
    }
    GRID_TRIG();
    #undef LOADROW
    #undef H3
    #undef EMIT
}

// ---------------- K2: selection (one CTA per batch) ----------------
__global__ void __launch_bounds__(1024) k_sel() {
    const int b = blockIdx.x, tid = threadIdx.x;
    __shared__ unsigned sfx[NBIN_];      // fine hist -> suffix sums -> cursors
    __shared__ unsigned sbcnt[NBUCK_];
    __shared__ int sB, sT;

    // prologue before consuming k_cand results
    sfx[tid] = 0u; sfx[tid + 1024] = 0u;
    g_cellcnt[b][tid] = 0u;              // reset cell counts for k_rank
    if (tid == 0) { sT = 0; g_ne[b] = 0; }

    GRID_SYNC();
    if (tid < NBUCK_) {
        unsigned cnt = g_bcnt[b][tid];
        sbcnt[tid] = cnt < CAPB_ ? cnt : CAPB_;
        g_bcnt[b][tid] = 0u;             // reset for next graph replay
    }
    __syncthreads();

    // coarse: largest bucket B* with (#keys in buckets >= B*) >= K
    if (tid == 0) {
        unsigned acc = 0; int Bst = 0;
        for (int bu = NBUCK_-1; bu >= 0; bu--) {
            acc += sbcnt[bu];
            if (acc >= K_) { Bst = bu; break; }
        }
        sB = Bst;
    }
    __syncthreads();
    const int Bst = sB;

    // fine histogram of keys in surviving buckets
    for (int bu = Bst; bu < NBUCK_; bu++) {
        int cnt = (int)sbcnt[bu];
        for (int i = tid; i < cnt; i += 1024) {
            unsigned long long key = g_bcand[b][bu][i];
            atomicAdd(&sfx[(unsigned)(key >> 44) & (NBIN_-1)], 1u);
        }
    }
    __syncthreads();

    // inclusive suffix sums: sfx[i] = #counted keys with bin >= i
    for (int off = 1; off < NBIN_; off <<= 1) {
        unsigned v0 = sfx[tid]      + ((tid + off        < NBIN_) ? sfx[tid + off]        : 0u);
        unsigned v1 = sfx[tid+1024] + ((tid + 1024 + off < NBIN_) ? sfx[tid + 1024 + off] : 0u);
        __syncthreads();
        sfx[tid] = v0; sfx[tid + 1024] = v1;
        __syncthreads();
    }

    // threshold bin T: largest bin with suffix >= K (stays 0 if total < K)
    for (int i = tid; i < NBIN_; i += 1024) {
        unsigned s = sfx[i];
        unsigned nx = (i + 1 < NBIN_) ? sfx[i+1] : 0u;
        if (s >= K_ && nx < K_) sT = i;
    }
    __syncthreads();
    const int T = sT;
    unsigned M = sfx[T]; if (M > SURV_) M = SURV_;

    // per-bin base/segend to gmem; then convert sfx to scatter cursors
    unsigned base0, base1;
    {
        unsigned s0 = sfx[tid],      n0 = (tid + 1 < NBIN_)        ? sfx[tid+1]      : 0u;
        unsigned s1 = sfx[tid+1024], n1 = (tid + 1024 + 1 < NBIN_) ? sfx[tid+1024+1] : 0u;
        g_base[b][tid] = n0;        g_segend[b][tid] = s0;
        g_base[b][tid+1024] = n1;   g_segend[b][tid+1024] = s1;
        base0 = n0; base1 = n1;
    }
    __syncthreads();
    sfx[tid] = base0; sfx[tid + 1024] = base1;
    __syncthreads();

    // compaction with shared cursors
    for (int bu = Bst; bu < NBUCK_; bu++) {
        int cnt = (int)sbcnt[bu];
        for (int i = tid; i < cnt; i += 1024) {
            unsigned long long key = g_bcand[b][bu][i];
            int bin = (int)((unsigned)(key >> 44) & (NBIN_-1));
            if (bin >= T) {
                unsigned pos = atomicAdd(&sfx[bin], 1u);
                if (pos < SURV_) g_surv[b][pos] = key;
            }
        }
    }

    // zero topk + publish M
    for (int i = tid; i < K_; i += 1024) g_topk[b][i] = 0ull;
    if (tid == 0) g_m[b] = (int)M;
    GRID_TRIG();
}

// ---------------- K3: exact rank + scatter + decode + cell count ----------------
// grid = (16, B), 256 threads; block covers surv slots [x*256, x*256+256)
__global__ void __launch_bounds__(256) k_rank(
    const float* __restrict__ deltas, const float* __restrict__ sizes,
    const int* __restrict__ p_stride, const int* __restrict__ p_offy,
    const int* __restrict__ p_offx)
{
    const int b = blockIdx.y, tid = threadIdx.x;
    const int p = blockIdx.x * 256 + tid;

    __shared__ unsigned long long skey[SPAN_];
    __shared__ int slo, shi;
    if (tid == 0) { slo = SURV_; shi = 0; }

    GRID_SYNC();
    const int M = g_m[b];
    if (blockIdx.x * 256 >= M) return;
    __syncthreads();

    unsigned long long key = 0ull;
    int s0 = 0, e = 0;
    if (p < M) {
        key = g_surv[b][p];
        int bin = (int)((unsigned)(key >> 44) & (NBIN_-1));
        s0 = (int)g_base[b][bin];
        e  = (int)g_segend[b][bin];
        if (e > SURV_) e = SURV_;
        atomicMin(&slo, s0);
        atomicMax(&shi, e);
    }
    __syncthreads();
    const int lo = slo, hi = shi;
    const int span = hi - lo;
    int rank = s0;

    if (span <= SPAN_) {
        for (int i = tid; i < span; i += 256) skey[i] = g_surv[b][lo + i];
        __syncthreads();
        if (p < M) {
            const unsigned long long* seg = &skey[s0 - lo];
            const int n = e - s0;
            int c0 = 0, c1 = 0, c2 = 0, c3 = 0;
            int m = 0;
            for (; m + 4 <= n; m += 4) {
                c0 += (seg[m]   > key);
                c1 += (seg[m+1] > key);
                c2 += (seg[m+2] > key);
                c3 += (seg[m+3] > key);
            }
            for (; m < n; m++) c0 += (seg[m] > key);
            rank += c0 + c1 + c2 + c3;
        }
    } else if (p < M) {
        // fallback: scan segment from global
        const unsigned long long* seg = g_surv[b];
        int c0 = 0, c1 = 0, c2 = 0, c3 = 0;
        int m = s0;
        for (; m + 4 <= e; m += 4) {
            c0 += (seg[m]   > key);
            c1 += (seg[m+1] > key);
            c2 += (seg[m+2] > key);
            c3 += (seg[m+3] > key);
        }
        for (; m < e; m++) c0 += (seg[m] > key);
        rank += c0 + c1 + c2 + c3;
    }

    if (p < M && rank < K_) {
        g_topk[b][rank] = key;
        // decode box (exact reference op order)
        const int stride = *p_stride, offy = *p_offy, offx = *p_offx;
        unsigned idx = ~(unsigned)key;
        int iw = (int)(idx & (W_-1)), ih = (int)(idx >> 10);
        float dx = deltas[((size_t)b*2 + 0)*HW_ + idx];
        float dy = deltas[((size_t)b*2 + 1)*HW_ + idx];
        float sx = sizes [((size_t)b*2 + 0)*HW_ + idx];
        float sy = sizes [((size_t)b*2 + 1)*HW_ + idx];
        float cx = (float)(iw*stride + offx) + dx;
        float cy = (float)(ih*stride + offy) + dy;
        float4 box;
        box.x = cx - sx*0.5f; box.y = cy - sy*0.5f;
        box.z = cx + sx*0.5f; box.w = cy + sy*0.5f;
        g_box[b][rank] = box;
        // cell binning (count phase), overlapped with gathers
        int ccx = min(31, max(0, (int)floorf((box.x+box.z)*0.5f*CELL_INV)));
        int ccy = min(31, max(0, (int)floorf((box.y+box.w)*0.5f*CELL_INV)));
        unsigned short cell = (unsigned short)(ccy*32 + ccx);
        g_cellof[b][rank] = cell;
        atomicAdd(&g_cellcnt[b][cell], 1u);
    }
    GRID_TRIG();
}

// ---------------- K4: cell scan + scatter, one CTA/batch ----------------
__global__ void __launch_bounds__(1024) k_bin() {
    const int b = blockIdx.x, tid = threadIdx.x;
    const int lane = tid & 31, wid = tid >> 5;
    __shared__ unsigned cellcnt[NCELL_];
    __shared__ unsigned wsum[32];

    GRID_SYNC();
    unsigned orig = g_cellcnt[b][tid];
    // exclusive scan over 1024 cells
    unsigned x = orig;
    for (int o = 1; o < 32; o <<= 1) {
        unsigned y = __shfl_up_sync(0xffffffffu, x, o);
        if (lane >= o) x += y;
    }
    if (lane == 31) wsum[wid] = x;
    __syncthreads();
    if (wid == 0) {
        unsigned s2 = wsum[lane];
        for (int o = 1; o < 32; o <<= 1) {
            unsigned y = __shfl_up_sync(0xffffffffu, s2, o);
            if (lane >= o) s2 += y;
        }
        wsum[lane] = s2;
    }
    __syncthreads();
    unsigned incl = x + (wid > 0 ? wsum[wid-1] : 0u);
    unsigned excl = incl - orig;
    g_cstart[b][tid] = (unsigned short)excl;
    if (tid == NCELL_-1) g_cstart[b][NCELL_] = (unsigned short)incl;
    cellcnt[tid] = excl;     // scatter cursors
    __syncthreads();

    #pragma unroll
    for (int k = 0; k < 2; k++) {
        int t = tid + k * 1024;
        if (g_topk[b][t] != 0ull) {
            unsigned p = atomicAdd(&cellcnt[g_cellof[b][t]], 1u);
            g_list[b][p] = (unsigned short)t;
        }
    }
    GRID_TRIG();
}

// ---------------- K5: chip-wide sparse edge detection ----------------
// grid = (8, B), 256 threads, 1 thread per box
__global__ void __launch_bounds__(256) k_edges() {
    const int b = blockIdx.y;
    const int t = blockIdx.x * 256 + threadIdx.x;
    GRID_SYNC();
    unsigned long long key = g_topk[b][t];
    if (key == 0ull) return;
    float4 bj = g_box[b][t];
    float aj = (bj.z - bj.x) * (bj.w - bj.y);
    int cc = g_cellof[b][t];
    int ccx = cc & 31, ccy = cc >> 5;
    int gy0 = max(ccy-1,0), gy1 = min(ccy+1,31);
    int gx0 = max(ccx-1,0), gx1 = min(ccx+1,31);
    for (int gy = gy0; gy <= gy1; gy++)
    for (int gx = gx0; gx <= gx1; gx++) {
        int c = gy*32 + gx;
        int ps = g_cstart[b][c], pe = g_cstart[b][c+1];
        for (int p = ps; p < pe; p++) {
            int i = g_list[b][p];
            if (i >= t) continue;
            float4 bi = g_box[b][i];
            float xx1 = fmaxf(bi.x, bj.x);
            float yy1 = fmaxf(bi.y, bj.y);
            float xx2 = fminf(bi.z, bj.z);
            float yy2 = fminf(bi.w, bj.w);
            float iw2 = xx2 - xx1, ih2 = yy2 - yy1;
            if (iw2 <= 0.f || ih2 <= 0.f) continue;
            float inter = iw2 * ih2;
            float ai = (bi.z - bi.x) * (bi.w - bi.y);
            float iou = inter / (ai + aj - inter + 1e-12f);
            if (iou > 0.5f) {
                int e = atomicAdd(&g_ne[b], 1);
                if (e < EMAX_) g_edges[b][e] = ((unsigned)t << 16) | (unsigned)i;
            }
        }
    }
    GRID_TRIG();
}

// ---------------- K6: greedy resolve + outputs, one CTA/batch ----------------
__global__ void __launch_bounds__(1024) k_final(float* __restrict__ out, int out_size) {
    const int b = blockIdx.x, tid = threadIdx.x;
    __shared__ unsigned edges[EMAX_];
    __shared__ unsigned char keep[K_];

    GRID_SYNC();
    int E = g_ne[b]; if (E > EMAX_) E = EMAX_;
    for (int i = tid; i < E; i += 1024) edges[i] = g_edges[b][i];
    #pragma unroll
    for (int k = 0; k < 2; k++) {
        int t = tid + k * 1024;
        keep[t] = (g_topk[b][t] != 0ull) ? 1 : 0;
    }
    __syncthreads();

    // exact greedy resolve: edges sorted ascending by suppressed index j
    if (tid == 0) {
        for (int a = 1; a < E; a++) {
            unsigned v = edges[a]; int q = a - 1;
            while (q >= 0 && edges[q] > v) { edges[q+1] = edges[q]; q--; }
            edges[q+1] = v;
        }
        for (int e = 0; e < E; e++) {
            int j = (int)(edges[e] >> 16), i = (int)(edges[e] & 0xffffu);
            if (keep[i]) keep[j] = 0;
        }
    }
    __syncthreads();

    // outputs: scores[B,K] ++ bboxes[B,K,4] ++ keep[B,K]
    const int so = 0, bo = B_*K_, ko = B_*K_*5;
    #pragma unroll
    for (int k = 0; k < 2; k++) {
        int t = tid + k * 1024;
        unsigned long long key = g_topk[b][t];
        float val = __uint_as_float((unsigned)(key >> 32));
        bool kp = keep[t] != 0;
        float4 box = g_box[b][t];
        int g = b*K_ + t;
        if (so + g < out_size) out[so + g] = kp ? val : 0.f;
        if (bo + g*4 + 3 < out_size) {
            float4 bx;
            bx.x = kp ? box.x : 0.f;
            bx.y = kp ? box.y : 0.f;
            bx.z = kp ? box.z : 0.f;
            bx.w = kp ? box.w : 0.f;
            *reinterpret_cast<float4*>(out + bo + g*4) = bx;
        }
        if (ko + g < out_size) out[ko + g] = kp ? 1.f : 0.f;
    }
}

// ---------------- launch (PDL-chained) ----------------
static void launch_ex(const void* func, dim3 grid, dim3 block, void** args, bool pdl) {
    cudaLaunchConfig_t cfg = {};
    cfg.gridDim = grid;
    cfg.blockDim = block;
    cfg.dynamicSmemBytes = 0;
    cfg.stream = 0;
    cudaLaunchAttribute attr[1];
    if (pdl) {
        attr[0].id = cudaLaunchAttributeProgrammaticStreamSerialization;
        attr[0].val.programmaticStreamSerializationAllowed = 1;
        cfg.attrs = attr;
        cfg.numAttrs = 1;
    }
    cudaLaunchKernelExC(&cfg, func, args);
}

extern "C" void kernel_launch(void* const* d_in, const int* in_sizes, int n_in,
                              void* d_out, int out_size) {
    (void)in_sizes; (void)n_in;
    const float* scores = (const float*)d_in[0];
    const float* deltas = (const float*)d_in[1];
    const float* sizes  = (const float*)d_in[2];
    const int* p_stride = (const int*)d_in[3];
    const int* p_offy   = (const int*)d_in[4];
    const int* p_offx   = (const int*)d_in[5];
    float* out = (float*)d_out;

    void* a1[] = { (void*)&scores };
    launch_ex((const void*)k_cand, dim3(H_ / RPB_, B_), dim3(256), a1, false);

    launch_ex((const void*)k_sel, dim3(B_), dim3(1024), nullptr, true);

    void* a3[] = { (void*)&deltas, (void*)&sizes,
                   (void*)&p_stride, (void*)&p_offy, (void*)&p_offx };
    launch_ex((const void*)k_rank, dim3(SURV_ / 256, B_), dim3(256), a3, true);

    launch_ex((const void*)k_bin, dim3(B_), dim3(1024), nullptr, true);

    launch_ex((const void*)k_edges, dim3(K_ / 256, B_), dim3(256), nullptr, true);

    void* a6[] = { (void*)&out, (void*)&out_size };
    launch_ex((const void*)k_final, dim3(B_), dim3(1024), a6, true);
}